// round 12
// baseline (speedup 1.0000x reference)
#include <cuda_runtime.h>
#include <cuda_bf16.h>
#include <cstdint>

// LSTM: B=32, T=1024, I=512, H=512, gates G=4H=2048
// out layout: outs[B][T][H] (16777216 floats) | h_T[B][H] | c_T[B][H]

#define NB 32
#define NT 1024
#define NI 512
#define NH 512
#define NG 2048

#define SCAN_BLOCKS 64
#define SCAN_THREADS 512

// ---------------- device scratch ----------------
__device__ float g_xg[(size_t)NT * NB * NG];      // [t][b][g]
__device__ unsigned g_bar;                        // monotonic barrier counter
__device__ __nv_bfloat16 g_xh[(size_t)NB * NT * NI];   // x hi split
__device__ __nv_bfloat16 g_xl[(size_t)NB * NT * NI];   // x lo split
__device__ __nv_bfloat16 g_wh[(size_t)NG * NI];        // W_ih hi split
__device__ __nv_bfloat16 g_wl[(size_t)NG * NI];        // W_ih lo split
// hidden state as bf16 hi/lo, [b][j] contiguous j, double-buffered
__device__ unsigned short g_hh[2][NB * NH];
__device__ unsigned short g_hl[2][NB * NH];

__device__ __forceinline__ float sigf(float x) {
    return 1.0f / (1.0f + __expf(-x));
}
__device__ __forceinline__ uint32_t smem_u32(const void* p) {
    uint32_t a;
    asm("{ .reg .u64 t; cvta.to.shared.u64 t, %1; cvt.u32.u64 %0, t; }" : "=r"(a) : "l"(p));
    return a;
}
__device__ __forceinline__ uint32_t swz(uint32_t off) { return off ^ ((off >> 3) & 0x70); }

#define CP_ASYNC16(dst, src) \
    asm volatile("cp.async.cg.shared.global [%0], [%1], 16;" :: "r"(dst), "l"(src))
#define CP_COMMIT() asm volatile("cp.async.commit_group;" ::: "memory")

#define LDSM_X4(r0, r1, r2, r3, a) \
    asm volatile("ldmatrix.sync.aligned.m8n8.x4.shared.b16 {%0,%1,%2,%3}, [%4];" \
                 : "=r"(r0), "=r"(r1), "=r"(r2), "=r"(r3) : "r"(a))

#define MMA16816(c, a, b0, b1) \
    asm volatile("mma.sync.aligned.m16n8k16.row.col.f32.bf16.bf16.f32 " \
                 "{%0,%1,%2,%3}, {%4,%5,%6,%7}, {%8,%9}, {%0,%1,%2,%3};" \
                 : "+f"((c)[0]), "+f"((c)[1]), "+f"((c)[2]), "+f"((c)[3]) \
                 : "r"((a)[0]), "r"((a)[1]), "r"((a)[2]), "r"((a)[3]), \
                   "r"(b0), "r"(b1))

// ---------------- split + init kernel (runs every replay) ----------------
__global__ void __launch_bounds__(256) k_split(const float* __restrict__ X,
                                               const float* __restrict__ Wih) {
    const int gtid = threadIdx.x + blockIdx.x * blockDim.x;
    const int nthr = gridDim.x * blockDim.x;

    if (gtid == 0) g_bar = 0u;
    for (int i = gtid; i < NB * NH / 8; i += nthr) {
        ((uint4*)&g_hh[0][0])[i] = make_uint4(0, 0, 0, 0);
        ((uint4*)&g_hl[0][0])[i] = make_uint4(0, 0, 0, 0);
    }

    for (int i = gtid; i < NB * NT * NI / 4; i += nthr) {
        float4 v = __ldg((const float4*)X + i);
        const float* f = (const float*)&v;
        unsigned hi[2] = {0, 0}, lo[2] = {0, 0};
#pragma unroll
        for (int j = 0; j < 4; j++) {
            __nv_bfloat16 h = __float2bfloat16_rn(f[j]);
            __nv_bfloat16 l = __float2bfloat16_rn(f[j] - __bfloat162float(h));
            hi[j >> 1] |= (unsigned)__bfloat16_as_ushort(h) << ((j & 1) * 16);
            lo[j >> 1] |= (unsigned)__bfloat16_as_ushort(l) << ((j & 1) * 16);
        }
        ((uint2*)g_xh)[i] = make_uint2(hi[0], hi[1]);
        ((uint2*)g_xl)[i] = make_uint2(lo[0], lo[1]);
    }
    for (int i = gtid; i < NG * NI / 4; i += nthr) {
        float4 v = __ldg((const float4*)Wih + i);
        const float* f = (const float*)&v;
        unsigned hi[2] = {0, 0}, lo[2] = {0, 0};
#pragma unroll
        for (int j = 0; j < 4; j++) {
            __nv_bfloat16 h = __float2bfloat16_rn(f[j]);
            __nv_bfloat16 l = __float2bfloat16_rn(f[j] - __bfloat162float(h));
            hi[j >> 1] |= (unsigned)__bfloat16_as_ushort(h) << ((j & 1) * 16);
            lo[j >> 1] |= (unsigned)__bfloat16_as_ushort(l) << ((j & 1) * 16);
        }
        ((uint2*)g_wh)[i] = make_uint2(hi[0], hi[1]);
        ((uint2*)g_wl)[i] = make_uint2(lo[0], lo[1]);
    }
}

// ---------------- mma.sync GEMM (unchanged — passing) ----------------
#define GHDR 1024
#define PANEL 16384
#define GBUF (4 * PANEL)

__device__ __forceinline__ void gemm_load_stage(uint32_t sb, uint32_t bufb, int kb,
                                                int tid, int m0, int n0) {
#pragma unroll
    for (int i = 0; i < 16; i++) {
        const int idx = tid + i * 256;
        const int panel = idx >> 10;
        const int row = (idx >> 3) & 127;
        const int sg = idx & 7;
        const __nv_bfloat16* src;
        if (panel == 0)      src = g_xh + (size_t)(m0 + row) * NI + kb + 8 * sg;
        else if (panel == 1) src = g_xl + (size_t)(m0 + row) * NI + kb + 8 * sg;
        else if (panel == 2) src = g_wh + (size_t)(n0 + row) * NI + kb + 8 * sg;
        else                 src = g_wl + (size_t)(n0 + row) * NI + kb + 8 * sg;
        CP_ASYNC16(sb + bufb + panel * PANEL + swz(row * 128 + sg * 16), src);
    }
}

__global__ void __launch_bounds__(256) k_gemm_mma(const float* __restrict__ bih,
                                                  const float* __restrict__ bhh) {
    extern __shared__ char smem[];
    const uint32_t sb = smem_u32(smem);
    const int tid = threadIdx.x;
    const int wid = tid >> 5;
    const int lane = tid & 31;
    const int n0 = blockIdx.x * 128;
    const int m0 = blockIdx.y * 128;
    float* sBias = (float*)smem;

    const int wm = wid & 1;
    const int wn = wid >> 1;

    if (tid < 128) sBias[tid] = __ldg(bih + n0 + tid) + __ldg(bhh + n0 + tid);

    uint32_t baseA[4], xorA[4];
#pragma unroll
    for (int mt = 0; mt < 4; mt++) {
        const int rA = wm * 64 + mt * 16 + (lane & 15);
        baseA[mt] = (uint32_t)rA * 128;
        xorA[mt] = (uint32_t)(rA & 7) << 4;
    }
    const uint32_t cA0 = (uint32_t)(lane >> 4) * 16;
    const int gB = lane >> 3;
    uint32_t baseB[2], xorB[2];
#pragma unroll
    for (int pr = 0; pr < 2; pr++) {
        const int rB = wn * 32 + pr * 16 + ((gB >> 1) << 3) + (lane & 7);
        baseB[pr] = (uint32_t)rB * 128;
        xorB[pr] = (uint32_t)(rB & 7) << 4;
    }
    const uint32_t cB0 = (uint32_t)(gB & 1) * 16;

    float acc[4][4][4];
#pragma unroll
    for (int mt = 0; mt < 4; mt++)
#pragma unroll
        for (int nt = 0; nt < 4; nt++)
#pragma unroll
            for (int e = 0; e < 4; e++) acc[mt][nt][e] = 0.0f;

    gemm_load_stage(sb, GHDR, 0, tid, m0, n0);
    CP_COMMIT();

    for (int s = 0; s < 8; s++) {
        const uint32_t bufb = GHDR + (uint32_t)(s & 1) * GBUF;
        if (s < 7) {
            gemm_load_stage(sb, GHDR + (uint32_t)((s + 1) & 1) * GBUF, (s + 1) * 64, tid, m0, n0);
            CP_COMMIT();
            asm volatile("cp.async.wait_group 1;" ::: "memory");
        } else {
            asm volatile("cp.async.wait_group 0;" ::: "memory");
        }
        __syncthreads();

        const uint32_t pAh = sb + bufb + 0 * PANEL;
        const uint32_t pAl = sb + bufb + 1 * PANEL;
        const uint32_t pBh = sb + bufb + 2 * PANEL;
        const uint32_t pBl = sb + bufb + 3 * PANEL;

#pragma unroll
        for (int k16 = 0; k16 < 4; k16++) {
            const uint32_t cA = (uint32_t)k16 * 32 + cA0;
            const uint32_t cB = (uint32_t)k16 * 32 + cB0;

            uint32_t ah[4][4], al[4][4], bh[2][4], bl[2][4];
#pragma unroll
            for (int mt = 0; mt < 4; mt++) {
                LDSM_X4(ah[mt][0], ah[mt][1], ah[mt][2], ah[mt][3],
                        pAh + baseA[mt] + (cA ^ xorA[mt]));
                LDSM_X4(al[mt][0], al[mt][1], al[mt][2], al[mt][3],
                        pAl + baseA[mt] + (cA ^ xorA[mt]));
            }
#pragma unroll
            for (int pr = 0; pr < 2; pr++) {
                LDSM_X4(bh[pr][0], bh[pr][1], bh[pr][2], bh[pr][3],
                        pBh + baseB[pr] + (cB ^ xorB[pr]));
                LDSM_X4(bl[pr][0], bl[pr][1], bl[pr][2], bl[pr][3],
                        pBl + baseB[pr] + (cB ^ xorB[pr]));
            }
#pragma unroll
            for (int mt = 0; mt < 4; mt++)
#pragma unroll
                for (int nt = 0; nt < 4; nt++) {
                    const int pr = nt >> 1;
                    const int sub = nt & 1;
                    MMA16816(acc[mt][nt], ah[mt], bh[pr][sub * 2], bh[pr][sub * 2 + 1]);
                    MMA16816(acc[mt][nt], al[mt], bh[pr][sub * 2], bh[pr][sub * 2 + 1]);
                    MMA16816(acc[mt][nt], ah[mt], bl[pr][sub * 2], bl[pr][sub * 2 + 1]);
                }
        }
        __syncthreads();
    }

    const int b = m0 >> 10;
#pragma unroll
    for (int mt = 0; mt < 4; mt++) {
        const int mrow0 = m0 + wm * 64 + mt * 16 + (lane >> 2);
        const int t0 = mrow0 & (NT - 1);
        const int t1 = (mrow0 + 8) & (NT - 1);
        float* d0 = g_xg + ((size_t)t0 * NB + b) * NG + n0;
        float* d1 = g_xg + ((size_t)t1 * NB + b) * NG + n0;
#pragma unroll
        for (int nt = 0; nt < 4; nt++) {
            const int bn = wn * 32 + nt * 8 + 2 * (lane & 3);
            const float bz0 = sBias[bn], bz1 = sBias[bn + 1];
            *(float2*)(d0 + bn) = make_float2(acc[mt][nt][0] + bz0, acc[mt][nt][1] + bz1);
            *(float2*)(d1 + bn) = make_float2(acc[mt][nt][2] + bz0, acc[mt][nt][3] + bz1);
        }
    }
}

// ---------------- persistent tensor-core scan (v4: 64 blocks x 8 units) ----------------
// Block owns j0 = bid*8..+7 => 32 gate rows m = q*8 + u. 16 warps:
// kc = wid>>1 (K-chunk of 64), mh = wid&1 (m-half 16 rows).
// W_hh frags (hi/lo) register-resident: ah[4][4], al[4][4] per warp.
// Per step: stage h hi/lo ([b][k] rows, 1040B) -> 16 LDSM + 48 mma per warp ->
// sRed[8][1024] scrambled -> 512-thread reduce (2 cols each) -> 256-thread
// finalize (c in regs) -> publish h hi/lo -> 64-block barrier.
#define HROW 1040                            // 520 bf16 per row (bank-shifted)
#define SOFF_HI 0
#define SOFF_LO (32 * HROW)                  // 33280
#define SOFF_RED (2 * 32 * HROW)             // 66560
#define SOFF_FIN (SOFF_RED + 8 * 1024 * 4)   // 99328
#define SCAN_SMEM (SOFF_FIN + 1024 * 4)      // 103424

__device__ __forceinline__ int scol(int m, int b) {
    return m * 32 + ((b + 8 * (m & 3)) & 31);
}

__global__ void __launch_bounds__(SCAN_THREADS, 1) k_scan(float* __restrict__ out,
                                                          const float* __restrict__ Whh) {
    extern __shared__ char sm[];
    const uint32_t sb = smem_u32(sm);
    float* sRed = (float*)(sm + SOFF_RED);
    float* sFin = (float*)(sm + SOFF_FIN);

    const int tid = threadIdx.x;
    const int bid = blockIdx.x;
    const int j0 = bid * 8;
    const int wid = tid >> 5;
    const int lane = tid & 31;
    const int kc = wid >> 1;          // K-chunk: k in [64kc, 64kc+64)
    const int mh = wid & 1;           // m-half: rows mh*16..+15

    // ---- stage W_hh panel (hi/lo bf16, 32 rows x 512) into the h region ----
    for (int idx = tid; idx < 32 * 512; idx += SCAN_THREADS) {
        const int m = idx >> 9;
        const int k = idx & 511;
        const float wv = __ldg(Whh + (size_t)((m >> 3) * 512 + j0 + (m & 7)) * NH + k);
        const __nv_bfloat16 h = __float2bfloat16_rn(wv);
        const __nv_bfloat16 l = __float2bfloat16_rn(wv - __bfloat162float(h));
        *(unsigned short*)(sm + SOFF_HI + m * HROW + 2 * k) = __bfloat16_as_ushort(h);
        *(unsigned short*)(sm + SOFF_LO + m * HROW + 2 * k) = __bfloat16_as_ushort(l);
    }
    __syncthreads();

    // ---- load W fragments (register-resident for the whole scan) ----
    uint32_t ah[4][4], al[4][4];
    {
        const uint32_t aRow = sb + SOFF_HI + (uint32_t)(mh * 16 + (lane & 15)) * HROW
                            + (uint32_t)(lane >> 4) * 16;
#pragma unroll
        for (int ks = 0; ks < 4; ks++) {
            const uint32_t cofs = (uint32_t)(kc * 64 + ks * 16) * 2;
            LDSM_X4(ah[ks][0], ah[ks][1], ah[ks][2], ah[ks][3], aRow + cofs);
            LDSM_X4(al[ks][0], al[ks][1], al[ks][2], al[ks][3],
                    aRow + (SOFF_LO - SOFF_HI) + cofs);
        }
    }
    __syncthreads();   // W region now free for per-step h staging

    // B ldmatrix per-lane base (batch rows)
    const int gB = lane >> 3;
    const uint32_t bBaseHi = sb + SOFF_HI
        + (uint32_t)(((gB >> 1) << 3) + (lane & 7)) * HROW + (uint32_t)(gB & 1) * 16;

    // finalize roles (tid < 256): fb = tid>>3 (batch), fu = tid&7 (unit)
    const int fb = tid >> 3;
    const int fu = tid & 7;

    float creg = 0.0f;
    float xg[4];
    if (tid < 256) {
        const float* xrow = g_xg + ((size_t)fb) * NG + j0 + fu;
#pragma unroll
        for (int q = 0; q < 4; q++) xg[q] = __ldcg(xrow + q * 512);
    }

    const int m0r = lane >> 2;          // c-frag row within m16 (and +8)
    const int bc0 = 2 * (lane & 3);     // c-frag col base within n8 tile

    for (int t = 0; t < NT; t++) {
        const int cur = t & 1;
        const int nxt = cur ^ 1;

        // ---- stage h hi/lo (32KB each) from L2 into smem [b][k] rows ----
        {
            const uint4* srcH = (const uint4*)&g_hh[cur][0];   // 2048 16B chunks
            const uint4* srcL = (const uint4*)&g_hl[cur][0];
#pragma unroll
            for (int i = 0; i < 4; i++) {
                const int f = tid + i * SCAN_THREADS;
                const int b = f >> 6;
                const int kch = f & 63;
                uint4 vh = __ldcg(srcH + f);
                uint4 vl = __ldcg(srcL + f);
                *(uint4*)(sm + SOFF_HI + b * HROW + kch * 16) = vh;
                *(uint4*)(sm + SOFF_LO + b * HROW + kch * 16) = vl;
            }
        }
        __syncthreads();

        // ---- tensor dot: 48 mma over this warp's (kc, mh) tile ----
        float acc[4][4];
#pragma unroll
        for (int nt = 0; nt < 4; nt++)
#pragma unroll
            for (int e = 0; e < 4; e++) acc[nt][e] = 0.0f;

#pragma unroll
        for (int ks = 0; ks < 4; ks++) {
            const uint32_t cofs = (uint32_t)(kc * 64 + ks * 16) * 2;
            uint32_t bh[2][4], bl[2][4];
#pragma unroll
            for (int nn = 0; nn < 2; nn++) {
                LDSM_X4(bh[nn][0], bh[nn][1], bh[nn][2], bh[nn][3],
                        bBaseHi + (uint32_t)nn * 16 * HROW + cofs);
                LDSM_X4(bl[nn][0], bl[nn][1], bl[nn][2], bl[nn][3],
                        bBaseHi + (SOFF_LO - SOFF_HI) + (uint32_t)nn * 16 * HROW + cofs);
            }
#pragma unroll
            for (int nn = 0; nn < 2; nn++)
#pragma unroll
                for (int sub = 0; sub < 2; sub++) {
                    const int nt = nn * 2 + sub;
                    MMA16816(acc[nt], ah[ks], bh[nn][sub * 2], bh[nn][sub * 2 + 1]);
                    MMA16816(acc[nt], al[ks], bh[nn][sub * 2], bh[nn][sub * 2 + 1]);
                    MMA16816(acc[nt], ah[ks], bl[nn][sub * 2], bl[nn][sub * 2 + 1]);
                }
        }

        // ---- store partials (scrambled columns; float2 conflict-free) ----
#pragma unroll
        for (int nt = 0; nt < 4; nt++) {
            const int b0 = nt * 8 + bc0;
            const int mA = mh * 16 + m0r;
            *(float2*)&sRed[kc * 1024 + scol(mA, b0)]     = make_float2(acc[nt][0], acc[nt][1]);
            *(float2*)&sRed[kc * 1024 + scol(mA + 8, b0)] = make_float2(acc[nt][2], acc[nt][3]);
        }
        __syncthreads();

        // ---- pre-reduce over 8 K-chunks (2 cols per thread) ----
        {
            float s0 = sRed[tid];
            float s1 = sRed[tid + 512];
#pragma unroll
            for (int r = 1; r < 8; r++) {
                s0 += sRed[r * 1024 + tid];
                s1 += sRed[r * 1024 + tid + 512];
            }
            sFin[tid] = s0;
            sFin[tid + 512] = s1;
        }
        __syncthreads();

        // ---- finalize ----
        if (tid < 256) {
            float gate[4];
#pragma unroll
            for (int q = 0; q < 4; q++) {
                const int m = q * 8 + fu;
                gate[q] = xg[q] + sFin[m * 32 + ((fb + 8 * (m & 3)) & 31)];
            }
            const float ig = sigf(gate[0]);
            const float fg = sigf(gate[1]);
            const float gv = tanhf(gate[2]);
            const float og = sigf(gate[3]);
            creg = fg * creg + ig * gv;
            const float hn = og * tanhf(creg);

            const int j = j0 + fu;
            out[((size_t)fb * NT + t) * NH + j] = hn;

            const __nv_bfloat16 hh = __float2bfloat16_rn(hn);
            const __nv_bfloat16 hl = __float2bfloat16_rn(hn - __bfloat162float(hh));
            g_hh[nxt][fb * NH + j] = __bfloat16_as_ushort(hh);
            g_hl[nxt][fb * NH + j] = __bfloat16_as_ushort(hl);

            if (t == NT - 1) {
                out[(size_t)NB * NT * NH + (size_t)fb * NH + j] = hn;
                out[(size_t)NB * NT * NH + (size_t)NB * NH + (size_t)fb * NH + j] = creg;
            }
            if (t + 1 < NT) {
                const float* xrow = g_xg + ((size_t)(t + 1) * NB + fb) * NG + j0 + fu;
#pragma unroll
                for (int q = 0; q < 4; q++) xg[q] = __ldcg(xrow + q * 512);
            }
        }
        __syncthreads();

        // ---- chip-wide barrier (monotonic counter, 64 arrivals) ----
        if (tid == 0) {
            __threadfence();
            atomicAdd(&g_bar, 1u);
            const unsigned target = (unsigned)SCAN_BLOCKS * (unsigned)(t + 1);
            volatile unsigned* bp2 = &g_bar;
            while (*bp2 < target) { __nanosleep(32); }
            __threadfence();
        }
        __syncthreads();
    }
}

// ---------------- launch ----------------
extern "C" void kernel_launch(void* const* d_in, const int* in_sizes, int n_in,
                              void* d_out, int out_size) {
    const float* x    = (const float*)d_in[0];
    const float* Wih  = (const float*)d_in[1];
    const float* Whh  = (const float*)d_in[2];
    const float* bih  = (const float*)d_in[3];
    const float* bhh  = (const float*)d_in[4];
    float* out = (float*)d_out;

    const int gemm_smem = GHDR + 2 * GBUF;   // 132,096 B
    cudaFuncSetAttribute(k_gemm_mma, cudaFuncAttributeMaxDynamicSharedMemorySize, gemm_smem);
    cudaFuncSetAttribute(k_scan, cudaFuncAttributeMaxDynamicSharedMemorySize, SCAN_SMEM);

    k_split<<<1024, 256>>>(x, Wih);

    dim3 ggrid(NG / 128, (NB * NT) / 128);   // (16, 256)
    k_gemm_mma<<<ggrid, 256, gemm_smem>>>(bih, bhh);

    k_scan<<<SCAN_BLOCKS, SCAN_THREADS, SCAN_SMEM>>>(out, Whh);
}

// round 13
// speedup vs baseline: 1.2553x; 1.2553x over previous
#include <cuda_runtime.h>
#include <cuda_bf16.h>
#include <cstdint>

// LSTM: B=32, T=1024, I=512, H=512, gates G=4H=2048
// out layout: outs[B][T][H] (16777216 floats) | h_T[B][H] | c_T[B][H]

#define NB 32
#define NT 1024
#define NI 512
#define NH 512
#define NG 2048

#define GROUPS 4
#define GBLK 32
#define GBATCH 8
#define SCAN_BLOCKS (GROUPS * GBLK)
#define SCAN_THREADS 512

// ---------------- device scratch ----------------
__device__ float g_xg[(size_t)NT * NB * NG];      // [t][b][g]
__device__ unsigned g_bars[GROUPS * 32];          // per-group monotonic counters (padded)
__device__ __nv_bfloat16 g_xh[(size_t)NB * NT * NI];   // x hi split
__device__ __nv_bfloat16 g_xl[(size_t)NB * NT * NI];   // x lo split
__device__ __nv_bfloat16 g_wh[(size_t)NG * NI];        // W_ih hi split
__device__ __nv_bfloat16 g_wl[(size_t)NG * NI];        // W_ih lo split
// hidden state as bf16 hi/lo, [b][j] contiguous j, double-buffered
__device__ unsigned short g_hh[2][NB * NH];
__device__ unsigned short g_hl[2][NB * NH];

__device__ __forceinline__ float sigf(float x) {
    return 1.0f / (1.0f + __expf(-x));
}
__device__ __forceinline__ uint32_t smem_u32(const void* p) {
    uint32_t a;
    asm("{ .reg .u64 t; cvta.to.shared.u64 t, %1; cvt.u32.u64 %0, t; }" : "=r"(a) : "l"(p));
    return a;
}
__device__ __forceinline__ uint32_t swz(uint32_t off) { return off ^ ((off >> 3) & 0x70); }

#define CP_ASYNC16(dst, src) \
    asm volatile("cp.async.cg.shared.global [%0], [%1], 16;" :: "r"(dst), "l"(src))
#define CP_COMMIT() asm volatile("cp.async.commit_group;" ::: "memory")

#define LDSM_X4(r0, r1, r2, r3, a) \
    asm volatile("ldmatrix.sync.aligned.m8n8.x4.shared.b16 {%0,%1,%2,%3}, [%4];" \
                 : "=r"(r0), "=r"(r1), "=r"(r2), "=r"(r3) : "r"(a))

#define MMA16816(c, a, b0, b1) \
    asm volatile("mma.sync.aligned.m16n8k16.row.col.f32.bf16.bf16.f32 " \
                 "{%0,%1,%2,%3}, {%4,%5,%6,%7}, {%8,%9}, {%0,%1,%2,%3};" \
                 : "+f"((c)[0]), "+f"((c)[1]), "+f"((c)[2]), "+f"((c)[3]) \
                 : "r"((a)[0]), "r"((a)[1]), "r"((a)[2]), "r"((a)[3]), \
                   "r"(b0), "r"(b1))

// pack two floats into hi-bf16x2 (ret) and lo-bf16x2 (out param)
__device__ __forceinline__ uint32_t pack_hilo2(float a, float b, uint32_t& lo) {
    __nv_bfloat16 ha = __float2bfloat16_rn(a);
    __nv_bfloat16 hb = __float2bfloat16_rn(b);
    __nv_bfloat16 la = __float2bfloat16_rn(a - __bfloat162float(ha));
    __nv_bfloat16 lb = __float2bfloat16_rn(b - __bfloat162float(hb));
    lo = (uint32_t)__bfloat16_as_ushort(la) | ((uint32_t)__bfloat16_as_ushort(lb) << 16);
    return (uint32_t)__bfloat16_as_ushort(ha) | ((uint32_t)__bfloat16_as_ushort(hb) << 16);
}

// ---------------- split + init kernel (runs every replay) ----------------
__global__ void __launch_bounds__(256) k_split(const float* __restrict__ X,
                                               const float* __restrict__ Wih) {
    const int gtid = threadIdx.x + blockIdx.x * blockDim.x;
    const int nthr = gridDim.x * blockDim.x;

    for (int i = gtid; i < GROUPS * 32; i += nthr) g_bars[i] = 0u;
    for (int i = gtid; i < NB * NH / 8; i += nthr) {
        ((uint4*)&g_hh[0][0])[i] = make_uint4(0, 0, 0, 0);
        ((uint4*)&g_hl[0][0])[i] = make_uint4(0, 0, 0, 0);
    }

    for (int i = gtid; i < NB * NT * NI / 4; i += nthr) {
        float4 v = __ldg((const float4*)X + i);
        const float* f = (const float*)&v;
        unsigned hi[2] = {0, 0}, lo[2] = {0, 0};
#pragma unroll
        for (int j = 0; j < 4; j++) {
            __nv_bfloat16 h = __float2bfloat16_rn(f[j]);
            __nv_bfloat16 l = __float2bfloat16_rn(f[j] - __bfloat162float(h));
            hi[j >> 1] |= (unsigned)__bfloat16_as_ushort(h) << ((j & 1) * 16);
            lo[j >> 1] |= (unsigned)__bfloat16_as_ushort(l) << ((j & 1) * 16);
        }
        ((uint2*)g_xh)[i] = make_uint2(hi[0], hi[1]);
        ((uint2*)g_xl)[i] = make_uint2(lo[0], lo[1]);
    }
    for (int i = gtid; i < NG * NI / 4; i += nthr) {
        float4 v = __ldg((const float4*)Wih + i);
        const float* f = (const float*)&v;
        unsigned hi[2] = {0, 0}, lo[2] = {0, 0};
#pragma unroll
        for (int j = 0; j < 4; j++) {
            __nv_bfloat16 h = __float2bfloat16_rn(f[j]);
            __nv_bfloat16 l = __float2bfloat16_rn(f[j] - __bfloat162float(h));
            hi[j >> 1] |= (unsigned)__bfloat16_as_ushort(h) << ((j & 1) * 16);
            lo[j >> 1] |= (unsigned)__bfloat16_as_ushort(l) << ((j & 1) * 16);
        }
        ((uint2*)g_wh)[i] = make_uint2(hi[0], hi[1]);
        ((uint2*)g_wl)[i] = make_uint2(lo[0], lo[1]);
    }
}

// ---------------- mma.sync GEMM (unchanged — passing) ----------------
#define GHDR 1024
#define PANEL 16384
#define GBUF (4 * PANEL)

__device__ __forceinline__ void gemm_load_stage(uint32_t sb, uint32_t bufb, int kb,
                                                int tid, int m0, int n0) {
#pragma unroll
    for (int i = 0; i < 16; i++) {
        const int idx = tid + i * 256;
        const int panel = idx >> 10;
        const int row = (idx >> 3) & 127;
        const int sg = idx & 7;
        const __nv_bfloat16* src;
        if (panel == 0)      src = g_xh + (size_t)(m0 + row) * NI + kb + 8 * sg;
        else if (panel == 1) src = g_xl + (size_t)(m0 + row) * NI + kb + 8 * sg;
        else if (panel == 2) src = g_wh + (size_t)(n0 + row) * NI + kb + 8 * sg;
        else                 src = g_wl + (size_t)(n0 + row) * NI + kb + 8 * sg;
        CP_ASYNC16(sb + bufb + panel * PANEL + swz(row * 128 + sg * 16), src);
    }
}

__global__ void __launch_bounds__(256) k_gemm_mma(const float* __restrict__ bih,
                                                  const float* __restrict__ bhh) {
    extern __shared__ char smem[];
    const uint32_t sb = smem_u32(smem);
    const int tid = threadIdx.x;
    const int wid = tid >> 5;
    const int lane = tid & 31;
    const int n0 = blockIdx.x * 128;
    const int m0 = blockIdx.y * 128;
    float* sBias = (float*)smem;

    const int wm = wid & 1;
    const int wn = wid >> 1;

    if (tid < 128) sBias[tid] = __ldg(bih + n0 + tid) + __ldg(bhh + n0 + tid);

    uint32_t baseA[4], xorA[4];
#pragma unroll
    for (int mt = 0; mt < 4; mt++) {
        const int rA = wm * 64 + mt * 16 + (lane & 15);
        baseA[mt] = (uint32_t)rA * 128;
        xorA[mt] = (uint32_t)(rA & 7) << 4;
    }
    const uint32_t cA0 = (uint32_t)(lane >> 4) * 16;
    const int gB = lane >> 3;
    uint32_t baseB[2], xorB[2];
#pragma unroll
    for (int pr = 0; pr < 2; pr++) {
        const int rB = wn * 32 + pr * 16 + ((gB >> 1) << 3) + (lane & 7);
        baseB[pr] = (uint32_t)rB * 128;
        xorB[pr] = (uint32_t)(rB & 7) << 4;
    }
    const uint32_t cB0 = (uint32_t)(gB & 1) * 16;

    float acc[4][4][4];
#pragma unroll
    for (int mt = 0; mt < 4; mt++)
#pragma unroll
        for (int nt = 0; nt < 4; nt++)
#pragma unroll
            for (int e = 0; e < 4; e++) acc[mt][nt][e] = 0.0f;

    gemm_load_stage(sb, GHDR, 0, tid, m0, n0);
    CP_COMMIT();

    for (int s = 0; s < 8; s++) {
        const uint32_t bufb = GHDR + (uint32_t)(s & 1) * GBUF;
        if (s < 7) {
            gemm_load_stage(sb, GHDR + (uint32_t)((s + 1) & 1) * GBUF, (s + 1) * 64, tid, m0, n0);
            CP_COMMIT();
            asm volatile("cp.async.wait_group 1;" ::: "memory");
        } else {
            asm volatile("cp.async.wait_group 0;" ::: "memory");
        }
        __syncthreads();

        const uint32_t pAh = sb + bufb + 0 * PANEL;
        const uint32_t pAl = sb + bufb + 1 * PANEL;
        const uint32_t pBh = sb + bufb + 2 * PANEL;
        const uint32_t pBl = sb + bufb + 3 * PANEL;

#pragma unroll
        for (int k16 = 0; k16 < 4; k16++) {
            const uint32_t cA = (uint32_t)k16 * 32 + cA0;
            const uint32_t cB = (uint32_t)k16 * 32 + cB0;

            uint32_t ah[4][4], al[4][4], bh[2][4], bl[2][4];
#pragma unroll
            for (int mt = 0; mt < 4; mt++) {
                LDSM_X4(ah[mt][0], ah[mt][1], ah[mt][2], ah[mt][3],
                        pAh + baseA[mt] + (cA ^ xorA[mt]));
                LDSM_X4(al[mt][0], al[mt][1], al[mt][2], al[mt][3],
                        pAl + baseA[mt] + (cA ^ xorA[mt]));
            }
#pragma unroll
            for (int pr = 0; pr < 2; pr++) {
                LDSM_X4(bh[pr][0], bh[pr][1], bh[pr][2], bh[pr][3],
                        pBh + baseB[pr] + (cB ^ xorB[pr]));
                LDSM_X4(bl[pr][0], bl[pr][1], bl[pr][2], bl[pr][3],
                        pBl + baseB[pr] + (cB ^ xorB[pr]));
            }
#pragma unroll
            for (int mt = 0; mt < 4; mt++)
#pragma unroll
                for (int nt = 0; nt < 4; nt++) {
                    const int pr = nt >> 1;
                    const int sub = nt & 1;
                    MMA16816(acc[mt][nt], ah[mt], bh[pr][sub * 2], bh[pr][sub * 2 + 1]);
                    MMA16816(acc[mt][nt], al[mt], bh[pr][sub * 2], bh[pr][sub * 2 + 1]);
                    MMA16816(acc[mt][nt], ah[mt], bl[pr][sub * 2], bl[pr][sub * 2 + 1]);
                }
        }
        __syncthreads();
    }

    const int b = m0 >> 10;
#pragma unroll
    for (int mt = 0; mt < 4; mt++) {
        const int mrow0 = m0 + wm * 64 + mt * 16 + (lane >> 2);
        const int t0 = mrow0 & (NT - 1);
        const int t1 = (mrow0 + 8) & (NT - 1);
        float* d0 = g_xg + ((size_t)t0 * NB + b) * NG + n0;
        float* d1 = g_xg + ((size_t)t1 * NB + b) * NG + n0;
#pragma unroll
        for (int nt = 0; nt < 4; nt++) {
            const int bn = wn * 32 + nt * 8 + 2 * (lane & 3);
            const float bz0 = sBias[bn], bz1 = sBias[bn + 1];
            *(float2*)(d0 + bn) = make_float2(acc[mt][nt][0] + bz0, acc[mt][nt][1] + bz1);
            *(float2*)(d1 + bn) = make_float2(acc[mt][nt][2] + bz0, acc[mt][nt][3] + bz1);
        }
    }
}

// ---------------- persistent tensor-core scan (v5: batch-grouped + mma) ----------------
// 4 independent groups x 32 blocks. Group gid owns batches [8gid, 8gid+8).
// Block owns 16 units j0 = (bid&31)*16 => 64 gate rows m = q*16+u.
// 16 warps: kc = wid>>1 (K-chunk 64), mh = wid&1 (rows mh*32..+31, 2 m16 tiles).
// W_hh hi/lo frags built DIRECTLY from global fp32 (A-frag lane map), register-
// resident. Per step: stage 8 batches of h hi/lo (16KB) -> 4 LDSM.x4 + 24 mma
// -> sRed[8][512] -> 512-thread reduce -> 128-thread finalize -> group barrier.
#define HROW 1040
#define SOFF_HI 0
#define SOFF_LO (GBATCH * HROW)              // 8320
#define SOFF_RED (2 * GBATCH * HROW)         // 16640
#define SOFF_FIN (SOFF_RED + 8 * 512 * 4)    // 33024
#define SCAN_SMEM (SOFF_FIN + 512 * 4)       // 35072

__global__ void __launch_bounds__(SCAN_THREADS, 1) k_scan(float* __restrict__ out,
                                                          const float* __restrict__ Whh) {
    extern __shared__ char sm[];
    const uint32_t sb = smem_u32(sm);
    float* sRed = (float*)(sm + SOFF_RED);
    float* sFin = (float*)(sm + SOFF_FIN);

    const int tid = threadIdx.x;
    const int bid = blockIdx.x;
    const int gid = bid >> 5;
    const int j0 = (bid & 31) * 16;
    const int wid = tid >> 5;
    const int lane = tid & 31;
    const int kc = wid >> 1;          // k in [64kc, 64kc+64)
    const int mh = wid & 1;           // rows mh*32 .. +31

    // ---- build W_hh fragments directly from global fp32 ----
    // A-frag m16k16 lane map: reg0=(r, c,c+1) reg1=(r+8, c) reg2=(r, c+8) reg3=(r+8, c+8)
    // with r = lane>>2, c = 2*(lane&3); local row m -> W row (m>>4)*512 + j0 + (m&15).
    uint32_t ah[2][4][4], al[2][4][4];
#pragma unroll
    for (int mt = 0; mt < 2; mt++) {
        const int mlo = mh * 32 + mt * 16 + (lane >> 2);       // local rows mlo, mlo+8
        const int mhi2 = mlo + 8;
        const size_t row0 = (size_t)((mlo >> 4) * 512 + j0 + (mlo & 15)) * NH;
        const size_t row1 = (size_t)((mhi2 >> 4) * 512 + j0 + (mhi2 & 15)) * NH;
#pragma unroll
        for (int ks = 0; ks < 4; ks++) {
            const int kb = kc * 64 + ks * 16 + 2 * (lane & 3);
            float2 v00 = *(const float2*)(Whh + row0 + kb);
            float2 v10 = *(const float2*)(Whh + row1 + kb);
            float2 v01 = *(const float2*)(Whh + row0 + kb + 8);
            float2 v11 = *(const float2*)(Whh + row1 + kb + 8);
            ah[mt][ks][0] = pack_hilo2(v00.x, v00.y, al[mt][ks][0]);
            ah[mt][ks][1] = pack_hilo2(v10.x, v10.y, al[mt][ks][1]);
            ah[mt][ks][2] = pack_hilo2(v01.x, v01.y, al[mt][ks][2]);
            ah[mt][ks][3] = pack_hilo2(v11.x, v11.y, al[mt][ks][3]);
        }
    }

    // B ldmatrix per-lane base: row = lane&7 (batch), k-byte = (lane>>3)*16
    const uint32_t bOff = (uint32_t)(lane & 7) * HROW + (uint32_t)(lane >> 3) * 16;

    // finalize roles (tid < 128): fb = tid&7 (batch in group), fu = tid>>3 (unit)
    const int fb = tid & 7;
    const int fu = tid >> 3;
    const int gb = gid * GBATCH + fb;          // global batch

    float creg = 0.0f;
    float xg[4];
    if (tid < 128) {
        const float* xrow = g_xg + ((size_t)gb) * NG + j0 + fu;
#pragma unroll
        for (int q = 0; q < 4; q++) xg[q] = __ldcg(xrow + q * 512);
    }

    const int m0r = lane >> 2;          // c-frag row within m16 (and +8)
    const int bc0 = 2 * (lane & 3);     // c-frag batch col base (n8)

    unsigned bar_tgt = 0;

    for (int t = 0; t < NT; t++) {
        const int cur = t & 1;
        const int nxt = cur ^ 1;

        // ---- stage group's h hi/lo (8KB each) from L2 into smem [b][k] ----
        {
            const uint4* srcH = (const uint4*)&g_hh[cur][gid * GBATCH * NH];   // 512 chunks
            const uint4* srcL = (const uint4*)&g_hl[cur][gid * GBATCH * NH];
            const int b = tid >> 6;
            const int kch = tid & 63;
            uint4 vh = __ldcg(srcH + tid);
            uint4 vl = __ldcg(srcL + tid);
            *(uint4*)(sm + SOFF_HI + b * HROW + kch * 16) = vh;
            *(uint4*)(sm + SOFF_LO + b * HROW + kch * 16) = vl;
        }
        __syncthreads();

        // ---- tensor dot: 4 LDSM.x4 + 24 mma ----
        float acc[2][4];
#pragma unroll
        for (int mt = 0; mt < 2; mt++)
#pragma unroll
            for (int e = 0; e < 4; e++) acc[mt][e] = 0.0f;

#pragma unroll
        for (int kh = 0; kh < 2; kh++) {       // k32 halves of this warp's k64
            const uint32_t cofs = (uint32_t)(kc * 64 + kh * 32) * 2;
            uint32_t bh[4], bl[4];
            LDSM_X4(bh[0], bh[1], bh[2], bh[3], sb + SOFF_HI + bOff + cofs);
            LDSM_X4(bl[0], bl[1], bl[2], bl[3], sb + SOFF_LO + bOff + cofs);
#pragma unroll
            for (int ki = 0; ki < 2; ki++) {   // k16 within the k32
                const int ks = kh * 2 + ki;
#pragma unroll
                for (int mt = 0; mt < 2; mt++) {
                    MMA16816(acc[mt], ah[mt][ks], bh[ki * 2], bh[ki * 2 + 1]);
                    MMA16816(acc[mt], al[mt][ks], bh[ki * 2], bh[ki * 2 + 1]);
                    MMA16816(acc[mt], ah[mt][ks], bl[ki * 2], bl[ki * 2 + 1]);
                }
            }
        }

        // ---- store partials: col = m*8 + b ----
#pragma unroll
        for (int mt = 0; mt < 2; mt++) {
            const int mA = mh * 32 + mt * 16 + m0r;
            *(float2*)&sRed[kc * 512 + mA * 8 + bc0] = make_float2(acc[mt][0], acc[mt][1]);
            *(float2*)&sRed[kc * 512 + (mA + 8) * 8 + bc0] = make_float2(acc[mt][2], acc[mt][3]);
        }
        __syncthreads();

        // ---- pre-reduce over 8 K-chunks ----
        {
            float s = sRed[tid];
#pragma unroll
            for (int r = 1; r < 8; r++) s += sRed[r * 512 + tid];
            sFin[tid] = s;
        }
        __syncthreads();

        // ---- finalize: col for (q, fu, fb) = (q*16+fu)*8 + fb = q*128 + tid ----
        if (tid < 128) {
            float gate[4];
#pragma unroll
            for (int q = 0; q < 4; q++) gate[q] = xg[q] + sFin[q * 128 + tid];
            const float ig = sigf(gate[0]);
            const float fg = sigf(gate[1]);
            const float gv = tanhf(gate[2]);
            const float og = sigf(gate[3]);
            creg = fg * creg + ig * gv;
            const float hn = og * tanhf(creg);

            const int j = j0 + fu;
            out[((size_t)gb * NT + t) * NH + j] = hn;

            const __nv_bfloat16 hh = __float2bfloat16_rn(hn);
            const __nv_bfloat16 hl = __float2bfloat16_rn(hn - __bfloat162float(hh));
            g_hh[nxt][gb * NH + j] = __bfloat16_as_ushort(hh);
            g_hl[nxt][gb * NH + j] = __bfloat16_as_ushort(hl);

            if (t == NT - 1) {
                out[(size_t)NB * NT * NH + (size_t)gb * NH + j] = hn;
                out[(size_t)NB * NT * NH + (size_t)NB * NH + (size_t)gb * NH + j] = creg;
            }
            if (t + 1 < NT) {
                const float* xrow = g_xg + ((size_t)(t + 1) * NB + gb) * NG + j0 + fu;
#pragma unroll
                for (int q = 0; q < 4; q++) xg[q] = __ldcg(xrow + q * 512);
            }
        }
        __syncthreads();

        // ---- group barrier (32 arrivals, monotonic counter) ----
        if (tid == 0) {
            __threadfence();
            atomicAdd(&g_bars[gid * 32], 1u);
            bar_tgt += GBLK;
            volatile unsigned* bp2 = &g_bars[gid * 32];
            while (*bp2 < bar_tgt) { __nanosleep(20); }
            __threadfence();
        }
        __syncthreads();
    }
}

// ---------------- launch ----------------
extern "C" void kernel_launch(void* const* d_in, const int* in_sizes, int n_in,
                              void* d_out, int out_size) {
    const float* x    = (const float*)d_in[0];
    const float* Wih  = (const float*)d_in[1];
    const float* Whh  = (const float*)d_in[2];
    const float* bih  = (const float*)d_in[3];
    const float* bhh  = (const float*)d_in[4];
    float* out = (float*)d_out;

    const int gemm_smem = GHDR + 2 * GBUF;   // 132,096 B
    cudaFuncSetAttribute(k_gemm_mma, cudaFuncAttributeMaxDynamicSharedMemorySize, gemm_smem);
    cudaFuncSetAttribute(k_scan, cudaFuncAttributeMaxDynamicSharedMemorySize, SCAN_SMEM);

    k_split<<<1024, 256>>>(x, Wih);

    dim3 ggrid(NG / 128, (NB * NT) / 128);   // (16, 256)
    k_gemm_mma<<<ggrid, 256, gemm_smem>>>(bih, bhh);

    k_scan<<<SCAN_BLOCKS, SCAN_THREADS, SCAN_SMEM>>>(out, Whh);
}

// round 14
// speedup vs baseline: 1.5232x; 1.2134x over previous
#include <cuda_runtime.h>
#include <cuda_bf16.h>
#include <cstdint>

// LSTM: B=32, T=1024, I=512, H=512, gates G=4H=2048
// out layout: outs[B][T][H] (16777216 floats) | h_T[B][H] | c_T[B][H]

#define NB 32
#define NT 1024
#define NI 512
#define NH 512
#define NG 2048

#define GROUPS 4
#define GBLK 32
#define GBATCH 8
#define SCAN_BLOCKS (GROUPS * GBLK)
#define SCAN_THREADS 512

// ---------------- device scratch ----------------
__device__ float g_xg[(size_t)NT * NB * NG];      // [t][b][g]
__device__ unsigned g_bars[GROUPS * 32];          // per-group monotonic counters (padded)
__device__ __nv_bfloat16 g_xh[(size_t)NB * NT * NI];   // x hi split
__device__ __nv_bfloat16 g_xl[(size_t)NB * NT * NI];   // x lo split
__device__ __nv_bfloat16 g_wh[(size_t)NG * NI];        // W_ih hi split
__device__ __nv_bfloat16 g_wl[(size_t)NG * NI];        // W_ih lo split
// hidden state as bf16 hi/lo, [b][j] contiguous j, double-buffered
__device__ unsigned short g_hh[2][NB * NH];
__device__ unsigned short g_hl[2][NB * NH];

__device__ __forceinline__ float sigf(float x) {
    return 1.0f / (1.0f + __expf(-x));
}
__device__ __forceinline__ float tanhfast(float x) {
    return 1.0f - 2.0f / (__expf(2.0f * x) + 1.0f);
}
__device__ __forceinline__ uint32_t smem_u32(const void* p) {
    uint32_t a;
    asm("{ .reg .u64 t; cvta.to.shared.u64 t, %1; cvt.u32.u64 %0, t; }" : "=r"(a) : "l"(p));
    return a;
}
__device__ __forceinline__ uint32_t swz(uint32_t off) { return off ^ ((off >> 3) & 0x70); }

#define CP_ASYNC16(dst, src) \
    asm volatile("cp.async.cg.shared.global [%0], [%1], 16;" :: "r"(dst), "l"(src))
#define CP_COMMIT() asm volatile("cp.async.commit_group;" ::: "memory")

#define LDSM_X4(r0, r1, r2, r3, a) \
    asm volatile("ldmatrix.sync.aligned.m8n8.x4.shared.b16 {%0,%1,%2,%3}, [%4];" \
                 : "=r"(r0), "=r"(r1), "=r"(r2), "=r"(r3) : "r"(a))

#define MMA16816(c, a, b0, b1) \
    asm volatile("mma.sync.aligned.m16n8k16.row.col.f32.bf16.bf16.f32 " \
                 "{%0,%1,%2,%3}, {%4,%5,%6,%7}, {%8,%9}, {%0,%1,%2,%3};" \
                 : "+f"((c)[0]), "+f"((c)[1]), "+f"((c)[2]), "+f"((c)[3]) \
                 : "r"((a)[0]), "r"((a)[1]), "r"((a)[2]), "r"((a)[3]), \
                   "r"(b0), "r"(b1))

// pack two floats into hi-bf16x2 (ret) and lo-bf16x2 (out param)
__device__ __forceinline__ uint32_t pack_hilo2(float a, float b, uint32_t& lo) {
    __nv_bfloat16 ha = __float2bfloat16_rn(a);
    __nv_bfloat16 hb = __float2bfloat16_rn(b);
    __nv_bfloat16 la = __float2bfloat16_rn(a - __bfloat162float(ha));
    __nv_bfloat16 lb = __float2bfloat16_rn(b - __bfloat162float(hb));
    lo = (uint32_t)__bfloat16_as_ushort(la) | ((uint32_t)__bfloat16_as_ushort(lb) << 16);
    return (uint32_t)__bfloat16_as_ushort(ha) | ((uint32_t)__bfloat16_as_ushort(hb) << 16);
}

// ---------------- split + init kernel (runs every replay) ----------------
__global__ void __launch_bounds__(256) k_split(const float* __restrict__ X,
                                               const float* __restrict__ Wih) {
    const int gtid = threadIdx.x + blockIdx.x * blockDim.x;
    const int nthr = gridDim.x * blockDim.x;

    for (int i = gtid; i < GROUPS * 32; i += nthr) g_bars[i] = 0u;
    for (int i = gtid; i < NB * NH / 8; i += nthr) {
        ((uint4*)&g_hh[0][0])[i] = make_uint4(0, 0, 0, 0);
        ((uint4*)&g_hl[0][0])[i] = make_uint4(0, 0, 0, 0);
    }

    for (int i = gtid; i < NB * NT * NI / 4; i += nthr) {
        float4 v = __ldg((const float4*)X + i);
        const float* f = (const float*)&v;
        unsigned hi[2] = {0, 0}, lo[2] = {0, 0};
#pragma unroll
        for (int j = 0; j < 4; j++) {
            __nv_bfloat16 h = __float2bfloat16_rn(f[j]);
            __nv_bfloat16 l = __float2bfloat16_rn(f[j] - __bfloat162float(h));
            hi[j >> 1] |= (unsigned)__bfloat16_as_ushort(h) << ((j & 1) * 16);
            lo[j >> 1] |= (unsigned)__bfloat16_as_ushort(l) << ((j & 1) * 16);
        }
        ((uint2*)g_xh)[i] = make_uint2(hi[0], hi[1]);
        ((uint2*)g_xl)[i] = make_uint2(lo[0], lo[1]);
    }
    for (int i = gtid; i < NG * NI / 4; i += nthr) {
        float4 v = __ldg((const float4*)Wih + i);
        const float* f = (const float*)&v;
        unsigned hi[2] = {0, 0}, lo[2] = {0, 0};
#pragma unroll
        for (int j = 0; j < 4; j++) {
            __nv_bfloat16 h = __float2bfloat16_rn(f[j]);
            __nv_bfloat16 l = __float2bfloat16_rn(f[j] - __bfloat162float(h));
            hi[j >> 1] |= (unsigned)__bfloat16_as_ushort(h) << ((j & 1) * 16);
            lo[j >> 1] |= (unsigned)__bfloat16_as_ushort(l) << ((j & 1) * 16);
        }
        ((uint2*)g_wh)[i] = make_uint2(hi[0], hi[1]);
        ((uint2*)g_wl)[i] = make_uint2(lo[0], lo[1]);
    }
}

// ---------------- mma.sync GEMM (unchanged — passing) ----------------
#define GHDR 1024
#define PANEL 16384
#define GBUF (4 * PANEL)

__device__ __forceinline__ void gemm_load_stage(uint32_t sb, uint32_t bufb, int kb,
                                                int tid, int m0, int n0) {
#pragma unroll
    for (int i = 0; i < 16; i++) {
        const int idx = tid + i * 256;
        const int panel = idx >> 10;
        const int row = (idx >> 3) & 127;
        const int sg = idx & 7;
        const __nv_bfloat16* src;
        if (panel == 0)      src = g_xh + (size_t)(m0 + row) * NI + kb + 8 * sg;
        else if (panel == 1) src = g_xl + (size_t)(m0 + row) * NI + kb + 8 * sg;
        else if (panel == 2) src = g_wh + (size_t)(n0 + row) * NI + kb + 8 * sg;
        else                 src = g_wl + (size_t)(n0 + row) * NI + kb + 8 * sg;
        CP_ASYNC16(sb + bufb + panel * PANEL + swz(row * 128 + sg * 16), src);
    }
}

__global__ void __launch_bounds__(256) k_gemm_mma(const float* __restrict__ bih,
                                                  const float* __restrict__ bhh) {
    extern __shared__ char smem[];
    const uint32_t sb = smem_u32(smem);
    const int tid = threadIdx.x;
    const int wid = tid >> 5;
    const int lane = tid & 31;
    const int n0 = blockIdx.x * 128;
    const int m0 = blockIdx.y * 128;
    float* sBias = (float*)smem;

    const int wm = wid & 1;
    const int wn = wid >> 1;

    if (tid < 128) sBias[tid] = __ldg(bih + n0 + tid) + __ldg(bhh + n0 + tid);

    uint32_t baseA[4], xorA[4];
#pragma unroll
    for (int mt = 0; mt < 4; mt++) {
        const int rA = wm * 64 + mt * 16 + (lane & 15);
        baseA[mt] = (uint32_t)rA * 128;
        xorA[mt] = (uint32_t)(rA & 7) << 4;
    }
    const uint32_t cA0 = (uint32_t)(lane >> 4) * 16;
    const int gB = lane >> 3;
    uint32_t baseB[2], xorB[2];
#pragma unroll
    for (int pr = 0; pr < 2; pr++) {
        const int rB = wn * 32 + pr * 16 + ((gB >> 1) << 3) + (lane & 7);
        baseB[pr] = (uint32_t)rB * 128;
        xorB[pr] = (uint32_t)(rB & 7) << 4;
    }
    const uint32_t cB0 = (uint32_t)(gB & 1) * 16;

    float acc[4][4][4];
#pragma unroll
    for (int mt = 0; mt < 4; mt++)
#pragma unroll
        for (int nt = 0; nt < 4; nt++)
#pragma unroll
            for (int e = 0; e < 4; e++) acc[mt][nt][e] = 0.0f;

    gemm_load_stage(sb, GHDR, 0, tid, m0, n0);
    CP_COMMIT();

    for (int s = 0; s < 8; s++) {
        const uint32_t bufb = GHDR + (uint32_t)(s & 1) * GBUF;
        if (s < 7) {
            gemm_load_stage(sb, GHDR + (uint32_t)((s + 1) & 1) * GBUF, (s + 1) * 64, tid, m0, n0);
            CP_COMMIT();
            asm volatile("cp.async.wait_group 1;" ::: "memory");
        } else {
            asm volatile("cp.async.wait_group 0;" ::: "memory");
        }
        __syncthreads();

        const uint32_t pAh = sb + bufb + 0 * PANEL;
        const uint32_t pAl = sb + bufb + 1 * PANEL;
        const uint32_t pBh = sb + bufb + 2 * PANEL;
        const uint32_t pBl = sb + bufb + 3 * PANEL;

#pragma unroll
        for (int k16 = 0; k16 < 4; k16++) {
            const uint32_t cA = (uint32_t)k16 * 32 + cA0;
            const uint32_t cB = (uint32_t)k16 * 32 + cB0;

            uint32_t ah[4][4], al[4][4], bh[2][4], bl[2][4];
#pragma unroll
            for (int mt = 0; mt < 4; mt++) {
                LDSM_X4(ah[mt][0], ah[mt][1], ah[mt][2], ah[mt][3],
                        pAh + baseA[mt] + (cA ^ xorA[mt]));
                LDSM_X4(al[mt][0], al[mt][1], al[mt][2], al[mt][3],
                        pAl + baseA[mt] + (cA ^ xorA[mt]));
            }
#pragma unroll
            for (int pr = 0; pr < 2; pr++) {
                LDSM_X4(bh[pr][0], bh[pr][1], bh[pr][2], bh[pr][3],
                        pBh + baseB[pr] + (cB ^ xorB[pr]));
                LDSM_X4(bl[pr][0], bl[pr][1], bl[pr][2], bl[pr][3],
                        pBl + baseB[pr] + (cB ^ xorB[pr]));
            }
#pragma unroll
            for (int mt = 0; mt < 4; mt++)
#pragma unroll
                for (int nt = 0; nt < 4; nt++) {
                    const int pr = nt >> 1;
                    const int sub = nt & 1;
                    MMA16816(acc[mt][nt], ah[mt], bh[pr][sub * 2], bh[pr][sub * 2 + 1]);
                    MMA16816(acc[mt][nt], al[mt], bh[pr][sub * 2], bh[pr][sub * 2 + 1]);
                    MMA16816(acc[mt][nt], ah[mt], bl[pr][sub * 2], bl[pr][sub * 2 + 1]);
                }
        }
        __syncthreads();
    }

    const int b = m0 >> 10;
#pragma unroll
    for (int mt = 0; mt < 4; mt++) {
        const int mrow0 = m0 + wm * 64 + mt * 16 + (lane >> 2);
        const int t0 = mrow0 & (NT - 1);
        const int t1 = (mrow0 + 8) & (NT - 1);
        float* d0 = g_xg + ((size_t)t0 * NB + b) * NG + n0;
        float* d1 = g_xg + ((size_t)t1 * NB + b) * NG + n0;
#pragma unroll
        for (int nt = 0; nt < 4; nt++) {
            const int bn = wn * 32 + nt * 8 + 2 * (lane & 3);
            const float bz0 = sBias[bn], bz1 = sBias[bn + 1];
            *(float2*)(d0 + bn) = make_float2(acc[mt][nt][0] + bz0, acc[mt][nt][1] + bz1);
            *(float2*)(d1 + bn) = make_float2(acc[mt][nt][2] + bz0, acc[mt][nt][3] + bz1);
        }
    }
}

// ---------------- persistent tensor-core scan (v6: spread finalize + acq/rel barrier) ----
// Structure as v5 (4 groups x 32 blocks, block = 16 units, W frags in regs).
// v6 changes: (1) gate reduce+activation spread over all 512 threads (one gate
// value each: q = tid>>7, pair = tid&127); (2) tanhfast everywhere; (3) barrier
// uses red.release.gpu + ld.acquire.gpu spin (no threadfence, no nanosleep).
#define HROW 1040
#define SOFF_HI 0
#define SOFF_LO (GBATCH * HROW)              // 8320
#define SOFF_RED (2 * GBATCH * HROW)         // 16640
#define SOFF_FIN (SOFF_RED + 8 * 512 * 4)    // 33024
#define SCAN_SMEM (SOFF_FIN + 512 * 4)       // 35072

__global__ void __launch_bounds__(SCAN_THREADS, 1) k_scan(float* __restrict__ out,
                                                          const float* __restrict__ Whh) {
    extern __shared__ char sm[];
    const uint32_t sb = smem_u32(sm);
    float* sRed = (float*)(sm + SOFF_RED);
    float* sFin = (float*)(sm + SOFF_FIN);

    const int tid = threadIdx.x;
    const int bid = blockIdx.x;
    const int gid = bid >> 5;
    const int j0 = (bid & 31) * 16;
    const int wid = tid >> 5;
    const int lane = tid & 31;
    const int kc = wid >> 1;          // k in [64kc, 64kc+64)
    const int mh = wid & 1;           // rows mh*32 .. +31

    // ---- build W_hh fragments directly from global fp32 (A-frag lane map) ----
    uint32_t ah[2][4][4], al[2][4][4];
#pragma unroll
    for (int mt = 0; mt < 2; mt++) {
        const int mlo = mh * 32 + mt * 16 + (lane >> 2);
        const int mhi2 = mlo + 8;
        const size_t row0 = (size_t)((mlo >> 4) * 512 + j0 + (mlo & 15)) * NH;
        const size_t row1 = (size_t)((mhi2 >> 4) * 512 + j0 + (mhi2 & 15)) * NH;
#pragma unroll
        for (int ks = 0; ks < 4; ks++) {
            const int kb = kc * 64 + ks * 16 + 2 * (lane & 3);
            float2 v00 = *(const float2*)(Whh + row0 + kb);
            float2 v10 = *(const float2*)(Whh + row1 + kb);
            float2 v01 = *(const float2*)(Whh + row0 + kb + 8);
            float2 v11 = *(const float2*)(Whh + row1 + kb + 8);
            ah[mt][ks][0] = pack_hilo2(v00.x, v00.y, al[mt][ks][0]);
            ah[mt][ks][1] = pack_hilo2(v10.x, v10.y, al[mt][ks][1]);
            ah[mt][ks][2] = pack_hilo2(v01.x, v01.y, al[mt][ks][2]);
            ah[mt][ks][3] = pack_hilo2(v11.x, v11.y, al[mt][ks][3]);
        }
    }

    // B ldmatrix per-lane base: row = lane&7 (batch), k-byte = (lane>>3)*16
    const uint32_t bOff = (uint32_t)(lane & 7) * HROW + (uint32_t)(lane >> 3) * 16;

    // gate-phase roles (ALL 512 threads): q = tid>>7, pair = tid&127
    const int gq = tid >> 7;
    const int gpair = tid & 127;               // fu*8 + fb
    const int gfb = gpair & 7;
    const int gfu = gpair >> 3;
    const int ggb = gid * GBATCH + gfb;        // global batch for gate thread

    // cell-phase roles (tid < 128): pair = tid
    const int cfb = tid & 7;
    const int cfu = tid >> 3;
    const int cgb = gid * GBATCH + cfb;

    float creg = 0.0f;

    // per-thread xg prefetch (one value: gate gq of unit gfu, batch ggb)
    float xgv = __ldcg(g_xg + ((size_t)ggb) * NG + gq * 512 + j0 + gfu);

    const int m0r = lane >> 2;
    const int bc0 = 2 * (lane & 3);

    unsigned bar_tgt = 0;
    unsigned* const barp = &g_bars[gid * 32];

    for (int t = 0; t < NT; t++) {
        const int cur = t & 1;
        const int nxt = cur ^ 1;

        // ---- stage group's h hi/lo (8KB each) ----
        {
            const uint4* srcH = (const uint4*)&g_hh[cur][gid * GBATCH * NH];
            const uint4* srcL = (const uint4*)&g_hl[cur][gid * GBATCH * NH];
            const int b = tid >> 6;
            const int kch = tid & 63;
            uint4 vh = __ldcg(srcH + tid);
            uint4 vl = __ldcg(srcL + tid);
            *(uint4*)(sm + SOFF_HI + b * HROW + kch * 16) = vh;
            *(uint4*)(sm + SOFF_LO + b * HROW + kch * 16) = vl;
        }
        __syncthreads();

        // ---- tensor dot: 4 LDSM.x4 + 24 mma ----
        float acc[2][4];
#pragma unroll
        for (int mt = 0; mt < 2; mt++)
#pragma unroll
            for (int e = 0; e < 4; e++) acc[mt][e] = 0.0f;

#pragma unroll
        for (int kh = 0; kh < 2; kh++) {
            const uint32_t cofs = (uint32_t)(kc * 64 + kh * 32) * 2;
            uint32_t bh[4], bl[4];
            LDSM_X4(bh[0], bh[1], bh[2], bh[3], sb + SOFF_HI + bOff + cofs);
            LDSM_X4(bl[0], bl[1], bl[2], bl[3], sb + SOFF_LO + bOff + cofs);
#pragma unroll
            for (int ki = 0; ki < 2; ki++) {
                const int ks = kh * 2 + ki;
#pragma unroll
                for (int mt = 0; mt < 2; mt++) {
                    MMA16816(acc[mt], ah[mt][ks], bh[ki * 2], bh[ki * 2 + 1]);
                    MMA16816(acc[mt], al[mt][ks], bh[ki * 2], bh[ki * 2 + 1]);
                    MMA16816(acc[mt], ah[mt][ks], bl[ki * 2], bl[ki * 2 + 1]);
                }
            }
        }

        // ---- store partials: col = m*8 + b = q*128 + pair ----
#pragma unroll
        for (int mt = 0; mt < 2; mt++) {
            const int mA = mh * 32 + mt * 16 + m0r;
            *(float2*)&sRed[kc * 512 + mA * 8 + bc0] = make_float2(acc[mt][0], acc[mt][1]);
            *(float2*)&sRed[kc * 512 + (mA + 8) * 8 + bc0] = make_float2(acc[mt][2], acc[mt][3]);
        }
        __syncthreads();

        // ---- gate phase: 512 threads, one gate value each ----
        {
            float s = xgv;
            const int col = gq * 128 + gpair;
#pragma unroll
            for (int r = 0; r < 8; r++) s += sRed[r * 512 + col];
            // prefetch next step's xg early (hidden across barrier)
            if (t + 1 < NT)
                xgv = __ldcg(g_xg + ((size_t)(t + 1) * NB + ggb) * NG + gq * 512 + j0 + gfu);
            const float act = (gq == 2) ? tanhfast(s) : sigf(s);
            sFin[gq * 128 + gpair] = act;
        }
        __syncthreads();

        // ---- cell phase: 128 threads ----
        if (tid < 128) {
            const float ig = sFin[tid];
            const float fg = sFin[128 + tid];
            const float gv = sFin[256 + tid];
            const float og = sFin[384 + tid];
            creg = fg * creg + ig * gv;
            const float hn = og * tanhfast(creg);

            const int j = j0 + cfu;
            out[((size_t)cgb * NT + t) * NH + j] = hn;

            const __nv_bfloat16 hh = __float2bfloat16_rn(hn);
            const __nv_bfloat16 hl = __float2bfloat16_rn(hn - __bfloat162float(hh));
            g_hh[nxt][cgb * NH + j] = __bfloat16_as_ushort(hh);
            g_hl[nxt][cgb * NH + j] = __bfloat16_as_ushort(hl);

            if (t == NT - 1) {
                out[(size_t)NB * NT * NH + (size_t)cgb * NH + j] = hn;
                out[(size_t)NB * NT * NH + (size_t)NB * NH + (size_t)cgb * NH + j] = creg;
            }
        }
        __syncthreads();

        // ---- group barrier: release-arrive + acquire-spin (cg::grid_sync pattern) ----
        if (tid == 0) {
            asm volatile("red.release.gpu.add.u32 [%0], %1;" :: "l"(barp), "r"(1u) : "memory");
            bar_tgt += GBLK;
            unsigned v;
            do {
                asm volatile("ld.acquire.gpu.u32 %0, [%1];" : "=r"(v) : "l"(barp) : "memory");
            } while (v < bar_tgt);
        }
        __syncthreads();
    }
}

// ---------------- launch ----------------
extern "C" void kernel_launch(void* const* d_in, const int* in_sizes, int n_in,
                              void* d_out, int out_size) {
    const float* x    = (const float*)d_in[0];
    const float* Wih  = (const float*)d_in[1];
    const float* Whh  = (const float*)d_in[2];
    const float* bih  = (const float*)d_in[3];
    const float* bhh  = (const float*)d_in[4];
    float* out = (float*)d_out;

    const int gemm_smem = GHDR + 2 * GBUF;   // 132,096 B
    cudaFuncSetAttribute(k_gemm_mma, cudaFuncAttributeMaxDynamicSharedMemorySize, gemm_smem);
    cudaFuncSetAttribute(k_scan, cudaFuncAttributeMaxDynamicSharedMemorySize, SCAN_SMEM);

    k_split<<<1024, 256>>>(x, Wih);

    dim3 ggrid(NG / 128, (NB * NT) / 128);   // (16, 256)
    k_gemm_mma<<<ggrid, 256, gemm_smem>>>(bih, bhh);

    k_scan<<<SCAN_BLOCKS, SCAN_THREADS, SCAN_SMEM>>>(out, Whh);
}